// round 16
// baseline (speedup 1.0000x reference)
#include <cuda_runtime.h>
#include <cuda_fp16.h>
#include <math.h>

#define S_LEN  4096
#define NH     16
#define NKV    4
#define HD     64
#define QSIZE  1024      // NH*HD
#define KVSIZE 256       // NKV*HD
#define QKV_N  1536      // QSIZE + 2*KVSIZE
#define IN_DIM 2048      // 2*HID
#define HID    1024

// Scratch (device globals; no allocations allowed)
__device__ float g_qkv[S_LEN * QKV_N];             // raw qkv (pre-rope)
__device__ float2 g_rope_tab[S_LEN * 32];          // (cos,sin) per (s,j)
// flash fp16 fragment tensors
__device__ unsigned g_qf16[16 * 256 * 4 * 32 * 4]; // [h][mt][kk][lane][4]
__device__ unsigned g_kf16[4 * 512 * 4 * 32 * 2];  // [kvh][tb][kk][lane][2]
__device__ unsigned g_vf16[4 * 256 * 8 * 32 * 2];  // [kvh][t16][nt][lane][2]
// GEMM operand fragments: A single fp16, B split (hi+lo)
__device__ uint4 g_hid_h[256 * 128 * 32];          // hidden A-frag
__device__ uint2 g_wqkv_h[192 * 128 * 32];         // w_qkv B-frag hi
__device__ uint2 g_wqkv_l[192 * 128 * 32];         //             lo
__device__ uint2 g_wo_h[128 * 64 * 32];            // w_o B-frag hi
__device__ uint2 g_wo_l[128 * 64 * 32];
__device__ uint4 g_attn_h[256 * 64 * 32];          // attn A-frag

// ---------------------------------------------------------------------------
// helpers
// ---------------------------------------------------------------------------
__device__ __forceinline__ void mma_f16(float* c, const unsigned* a, const unsigned* b) {
    asm volatile(
        "mma.sync.aligned.m16n8k16.row.col.f32.f16.f16.f32 "
        "{%0,%1,%2,%3}, {%4,%5,%6,%7}, {%8,%9}, {%0,%1,%2,%3};"
        : "+f"(c[0]), "+f"(c[1]), "+f"(c[2]), "+f"(c[3])
        : "r"(a[0]), "r"(a[1]), "r"(a[2]), "r"(a[3]), "r"(b[0]), "r"(b[1]));
}

__device__ __forceinline__ unsigned pack_h2(float lo, float hi) {
    __half2 h = __floats2half2_rn(lo, hi);
    return *(unsigned*)&h;
}

__device__ __forceinline__ void split_h2(float a, float b, unsigned& hi, unsigned& lo) {
    __half ha = __float2half_rn(a), hb = __float2half_rn(b);
    float ra = a - __half2float(ha), rb = b - __half2float(hb);
    __half2 h = __halves2half2(ha, hb);
    hi = *(unsigned*)&h;
    lo = pack_h2(ra, rb);
}

__device__ __forceinline__ void cp_async16(void* smem, const void* gmem) {
    unsigned s = (unsigned)__cvta_generic_to_shared(smem);
    asm volatile("cp.async.cg.shared.global [%0], [%1], 16;" :: "r"(s), "l"(gmem));
}
#define CP_COMMIT() asm volatile("cp.async.commit_group;")
#define CP_WAIT_ALL() asm volatile("cp.async.wait_group 0;")

// ---------------------------------------------------------------------------
// MERGED: rope table + input conversion (independent work, one launch).
// Units (warp-granular): rope 4096 | hidden A 32768 | w_qkv B 24576 | w_o B 8192
// ---------------------------------------------------------------------------
__global__ __launch_bounds__(256) void convert_all_kernel(
    const int* __restrict__ positions,
    const float* __restrict__ hidden, const float* __restrict__ w_qkv,
    const float* __restrict__ w_o)
{
    const int wid  = (blockIdx.x * blockDim.x + threadIdx.x) >> 5;
    const int lane = threadIdx.x & 31;
    const int g = lane >> 2, t = lane & 3;

    if (wid < 4096) {
        // ---- rope table: s = wid, j = lane (invf in fp64, phase fp32) ----
        double invf = exp(-(double)lane * (1.0 / 32.0) * log(10000.0));
        float f = (float)positions[wid] * (float)invf;
        float sn, c;
        sincosf(f, &sn, &c);
        g_rope_tab[wid * 32 + lane] = make_float2(c, sn);
    } else if (wid < 4096 + 32768) {
        const int u = wid - 4096;
        const int mt = u >> 7, kk = u & 127;
        const float* A = hidden + (size_t)(mt * 16) * IN_DIM + kk * 16;
        float2 a0 = *(const float2*)(A + (size_t)g * IN_DIM + 2 * t);
        float2 a1 = *(const float2*)(A + (size_t)(g + 8) * IN_DIM + 2 * t);
        float2 a2 = *(const float2*)(A + (size_t)g * IN_DIM + 2 * t + 8);
        float2 a3 = *(const float2*)(A + (size_t)(g + 8) * IN_DIM + 2 * t + 8);
        uint4 h;
        h.x = pack_h2(a0.x, a0.y);
        h.y = pack_h2(a1.x, a1.y);
        h.z = pack_h2(a2.x, a2.y);
        h.w = pack_h2(a3.x, a3.y);
        g_hid_h[(size_t)u * 32 + lane] = h;
    } else if (wid < 4096 + 32768 + 24576) {
        const int u = wid - 4096 - 32768;
        const int nt = u >> 7, kk = u & 127;
        const float* B = w_qkv + (size_t)(nt * 8 + g) * IN_DIM + kk * 16;
        float2 b0 = *(const float2*)(B + 2 * t);
        float2 b1 = *(const float2*)(B + 2 * t + 8);
        uint2 h, l;
        split_h2(b0.x, b0.y, h.x, l.x);
        split_h2(b1.x, b1.y, h.y, l.y);
        size_t o = (size_t)u * 32 + lane;
        g_wqkv_h[o] = h; g_wqkv_l[o] = l;
    } else if (wid < 4096 + 32768 + 24576 + 8192) {
        const int u = wid - 4096 - 32768 - 24576;
        const int nt = u >> 6, kk = u & 63;
        const float* B = w_o + (size_t)(nt * 8 + g) * QSIZE + kk * 16;
        float2 b0 = *(const float2*)(B + 2 * t);
        float2 b1 = *(const float2*)(B + 2 * t + 8);
        uint2 h, l;
        split_h2(b0.x, b0.y, h.x, l.x);
        split_h2(b1.x, b1.y, h.y, l.y);
        size_t o = (size_t)u * 32 + lane;
        g_wo_h[o] = h; g_wo_l[o] = l;
    }
}

// ---------------------------------------------------------------------------
// NT GEMM on fragment-major operands, A single fp16, B split (R14-validated)
// ---------------------------------------------------------------------------
__global__ __launch_bounds__(256, 1) void gemm_frag_kernel(
    const uint4* __restrict__ Ah,
    const uint2* __restrict__ Bh, const uint2* __restrict__ Bl,
    float* __restrict__ C, int Nn, int Kk)
{
    const int lane = threadIdx.x & 31;
    const int w = threadIdx.x >> 5;
    const int mt0 = blockIdx.y * 8 + (w >> 2) * 4;
    const int nt0 = blockIdx.x * 16 + (w & 3) * 4;

    const uint4 *pah[4];
    const uint2 *pbh[4], *pbl[4];
#pragma unroll
    for (int i = 0; i < 4; i++) {
        size_t oa = ((size_t)(mt0 + i) * Kk) * 32 + lane;
        size_t ob = ((size_t)(nt0 + i) * Kk) * 32 + lane;
        pah[i] = Ah + oa;
        pbh[i] = Bh + ob; pbl[i] = Bl + ob;
    }

    float acc[4][4][4];
#pragma unroll
    for (int i = 0; i < 4; i++)
#pragma unroll
        for (int j = 0; j < 4; j++)
#pragma unroll
            for (int e = 0; e < 4; e++) acc[i][j][e] = 0.f;

    uint4 ah[2][4];
    uint2 bh[2][4], bl[2][4];
#pragma unroll
    for (int i = 0; i < 4; i++) {
        ah[0][i] = pah[i][0];
        bh[0][i] = pbh[i][0]; bl[0][i] = pbl[i][0];
    }

    for (int kk = 0; kk < Kk; kk++) {
        const int cur = kk & 1, nxt = cur ^ 1;
        if (kk + 1 < Kk) {
            int off = (kk + 1) * 32;
#pragma unroll
            for (int i = 0; i < 4; i++) {
                ah[nxt][i] = pah[i][off];
                bh[nxt][i] = pbh[i][off]; bl[nxt][i] = pbl[i][off];
            }
        }
#pragma unroll
        for (int i = 0; i < 4; i++)
#pragma unroll
            for (int j = 0; j < 4; j++) {
                mma_f16(acc[i][j], (const unsigned*)&ah[cur][i], (const unsigned*)&bh[cur][j]);
                mma_f16(acc[i][j], (const unsigned*)&ah[cur][i], (const unsigned*)&bl[cur][j]);
            }
    }

    const int g = lane >> 2, tq = lane & 3;
#pragma unroll
    for (int i = 0; i < 4; i++) {
        int r0 = (mt0 + i) * 16 + g;
#pragma unroll
        for (int j = 0; j < 4; j++) {
            int c0 = (nt0 + j) * 8 + tq * 2;
            float2 lo = {acc[i][j][0], acc[i][j][1]};
            float2 hi = {acc[i][j][2], acc[i][j][3]};
            *(float2*)(C + (size_t)r0 * Nn + c0)       = lo;
            *(float2*)(C + (size_t)(r0 + 8) * Nn + c0) = hi;
        }
    }
}

// ---------------------------------------------------------------------------
// Convert qkv -> flash fp16 fragments WITH RoPE fused (validated in R10)
// ---------------------------------------------------------------------------
__global__ __launch_bounds__(256) void convert_frag_kernel()
{
    const int wid  = (blockIdx.x * blockDim.x + threadIdx.x) >> 5;
    const int lane = threadIdx.x & 31;
    const int g = lane >> 2, t = lane & 3;

    if (wid < 4096) {
        const int h = wid >> 8, mt = wid & 255;
        const int s0 = mt * 16;
        const float* Q = g_qkv + (size_t)s0 * QKV_N + h * 64;
        unsigned* dst = g_qf16 + ((size_t)(h * 256 + mt) * 4) * 128;
#pragma unroll
        for (int kk = 0; kk < 2; kk++) {
            int c = kk * 16 + 2 * t;
            uint4 wl, wh;
            unsigned* pl = (unsigned*)&wl;
            unsigned* ph = (unsigned*)&wh;
#pragma unroll
            for (int pi = 0; pi < 2; pi++) {
                int cc = c + pi * 8;
#pragma unroll
                for (int ri = 0; ri < 2; ri++) {
                    int r = g + ri * 8;
                    float2 xa = *(const float2*)(Q + (size_t)r * QKV_N + cc);
                    float2 xb = *(const float2*)(Q + (size_t)r * QKV_N + cc + 32);
                    float4 tb = *(const float4*)(g_rope_tab + (size_t)(s0 + r) * 32 + cc);
                    pl[pi * 2 + ri] = pack_h2((xa.x * tb.x - xb.x * tb.y) * 0.125f,
                                              (xa.y * tb.z - xb.y * tb.w) * 0.125f);
                    ph[pi * 2 + ri] = pack_h2((xb.x * tb.x + xa.x * tb.y) * 0.125f,
                                              (xb.y * tb.z + xa.y * tb.w) * 0.125f);
                }
            }
            *(uint4*)(dst + ((kk * 32 + lane) << 2))       = wl;
            *(uint4*)(dst + (((kk + 2) * 32 + lane)) * 4)  = wh;
        }
    } else if (wid < 4096 + 2048) {
        const int u = wid - 4096;
        const int kvh = u >> 9, tb = u & 511;
        const int s = tb * 8 + g;
        const float* K = g_qkv + (size_t)s * QKV_N + QSIZE + kvh * 64;
        unsigned* dst = g_kf16 + ((size_t)(kvh * 512 + tb) * 4) * 64;
#pragma unroll
        for (int kk = 0; kk < 2; kk++) {
            int c = kk * 16 + 2 * t;
            uint2 wl, wh;
            unsigned* pl = (unsigned*)&wl;
            unsigned* ph = (unsigned*)&wh;
#pragma unroll
            for (int pi = 0; pi < 2; pi++) {
                int cc = c + pi * 8;
                float2 xa = *(const float2*)(K + cc);
                float2 xb = *(const float2*)(K + cc + 32);
                float4 tbv = *(const float4*)(g_rope_tab + (size_t)s * 32 + cc);
                pl[pi] = pack_h2(xa.x * tbv.x - xb.x * tbv.y,
                                 xa.y * tbv.z - xb.y * tbv.w);
                ph[pi] = pack_h2(xb.x * tbv.x + xa.x * tbv.y,
                                 xb.y * tbv.z + xa.y * tbv.w);
            }
            *(uint2*)(dst + ((kk * 32 + lane) << 1))      = wl;
            *(uint2*)(dst + (((kk + 2) * 32 + lane)) * 2) = wh;
        }
    } else if (wid < 4096 + 2048 + 1024) {
        const int u = wid - 4096 - 2048;
        const int kvh = u >> 8, t16 = u & 255;
        const float* V = g_qkv + (size_t)(t16 * 16) * QKV_N + QSIZE + KVSIZE + kvh * 64;
        unsigned* dst = g_vf16 + ((size_t)(kvh * 256 + t16) * 8) * 64;
#pragma unroll
        for (int nt = 0; nt < 8; nt++) {
            int d = nt * 8 + g;
            float v0 = V[(size_t)(2 * t) * QKV_N + d];
            float v1 = V[(size_t)(2 * t + 1) * QKV_N + d];
            float v2 = V[(size_t)(2 * t + 8) * QKV_N + d];
            float v3 = V[(size_t)(2 * t + 9) * QKV_N + d];
            uint2 w;
            w.x = pack_h2(v0, v1);
            w.y = pack_h2(v2, v3);
            *(uint2*)(dst + ((nt * 32 + lane) << 1)) = w;
        }
    }
}

// ---------------------------------------------------------------------------
// Causal GQA flash attention — 8 warps, 2 m-tiles/warp, paired qb, cp.async
// double buffer with running toggle (identical to R15 best).
// ---------------------------------------------------------------------------
__global__ __launch_bounds__(256, 1) void flash_tc_kernel()
{
    __shared__ __align__(16) unsigned smK[2][2048];  // 8KB per buffer
    __shared__ __align__(16) unsigned smV[2][2048];

    const int tid  = threadIdx.x;
    const int lane = tid & 31;
    const int wrp  = tid >> 5;               // 0..7
    const int hw   = wrp >> 1;               // head-in-group 0..3
    const int mp   = wrp & 1;                // m-tile pair 0..1
    const int pair = blockIdx.x;             // 0..31
    const int kvh = blockIdx.y;
    const int h = kvh * 4 + hw;

    const int gq = lane >> 2;
    const int tq = lane & 3;
    const int qrowA = (mp * 32) + gq;
    const int qrowB = (mp * 32) + 16 + gq;

    const unsigned* kf0 = g_kf16 + (size_t)kvh * 512 * 4 * 64;
    const unsigned* vf0 = g_vf16 + (size_t)kvh * 256 * 8 * 64;

    cp_async16(&smK[0][tid * 8],     kf0 + tid * 8);
    cp_async16(&smK[0][tid * 8 + 4], kf0 + tid * 8 + 4);
    cp_async16(&smV[0][tid * 8],     vf0 + tid * 8);
    cp_async16(&smV[0][tid * 8 + 4], vf0 + tid * 8 + 4);
    CP_COMMIT();

    int cur = 0;

#pragma unroll
    for (int half = 0; half < 2; half++) {
        const int qb = half ? pair : (63 - pair);
        const int mtA = qb * 4 + mp * 2;
        const int mtB = mtA + 1;

        unsigned qaA[4][4], qaB[4][4];
        {
            const uint4* qfA = (const uint4*)g_qf16 + ((size_t)(h * 256 + mtA) * 4) * 32;
            const uint4* qfB = (const uint4*)g_qf16 + ((size_t)(h * 256 + mtB) * 4) * 32;
#pragma unroll
            for (int kk = 0; kk < 4; kk++) {
                *(uint4*)qaA[kk] = qfA[kk * 32 + lane];
                *(uint4*)qaB[kk] = qfB[kk * 32 + lane];
            }
        }

        float mA[2] = {-1e30f, -1e30f}, lA[2] = {0.f, 0.f};
        float mB[2] = {-1e30f, -1e30f}, lB[2] = {0.f, 0.f};
        float accA[8][4], accB[8][4];
#pragma unroll
        for (int i = 0; i < 8; i++)
#pragma unroll
            for (int j = 0; j < 4; j++) { accA[i][j] = 0.f; accB[i][j] = 0.f; }

        for (int kb = 0; kb <= qb; kb++) {
            const int nxt = cur ^ 1;
            CP_WAIT_ALL();
            __syncthreads();

            const bool more = (kb < qb);
            if (more) {
                const unsigned* kn = kf0 + (size_t)(kb + 1) * 2048;
                const unsigned* vn = vf0 + (size_t)(kb + 1) * 2048;
                cp_async16(&smK[nxt][tid * 8],     kn + tid * 8);
                cp_async16(&smK[nxt][tid * 8 + 4], kn + tid * 8 + 4);
                cp_async16(&smV[nxt][tid * 8],     vn + tid * 8);
                cp_async16(&smV[nxt][tid * 8 + 4], vn + tid * 8 + 4);
                CP_COMMIT();
            } else if (half == 0) {
                cp_async16(&smK[nxt][tid * 8],     kf0 + tid * 8);
                cp_async16(&smK[nxt][tid * 8 + 4], kf0 + tid * 8 + 4);
                cp_async16(&smV[nxt][tid * 8],     vf0 + tid * 8);
                cp_async16(&smV[nxt][tid * 8 + 4], vf0 + tid * 8 + 4);
                CP_COMMIT();
            }

            const uint2* Ks = (const uint2*)smK[cur];
            const uint2* Vs = (const uint2*)smV[cur];

            float sA[8][4], sB[8][4];
#pragma unroll
            for (int nt = 0; nt < 8; nt++)
#pragma unroll
                for (int j = 0; j < 4; j++) { sA[nt][j] = 0.f; sB[nt][j] = 0.f; }
#pragma unroll
            for (int kk = 0; kk < 4; kk++) {
#pragma unroll
                for (int nt = 0; nt < 8; nt++) {
                    uint2 b = Ks[((nt << 2) | kk) * 32 + lane];
                    mma_f16(sA[nt], qaA[kk], (const unsigned*)&b);
                    mma_f16(sB[nt], qaB[kk], (const unsigned*)&b);
                }
            }

            if (kb == qb) {
#pragma unroll
                for (int nt = 0; nt < 8; nt++) {
                    int cb = (nt << 3) + (tq << 1);
                    if (cb     > qrowA)     sA[nt][0] = -1e30f;
                    if (cb + 1 > qrowA)     sA[nt][1] = -1e30f;
                    if (cb     > qrowA + 8) sA[nt][2] = -1e30f;
                    if (cb + 1 > qrowA + 8) sA[nt][3] = -1e30f;
                    if (cb     > qrowB)     sB[nt][0] = -1e30f;
                    if (cb + 1 > qrowB)     sB[nt][1] = -1e30f;
                    if (cb     > qrowB + 8) sB[nt][2] = -1e30f;
                    if (cb + 1 > qrowB + 8) sB[nt][3] = -1e30f;
                }
            }

            unsigned paA[4][4], paB[4][4];
#pragma unroll
            for (int u = 0; u < 2; u++) {
                float (*s)[4]   = u ? sB : sA;
                float* m_s      = u ? mB : mA;
                float* l_s      = u ? lB : lA;
                float (*acc)[4] = u ? accB : accA;
                unsigned (*pa)[4] = u ? paB : paA;

                float mx0 = -1e30f, mx1 = -1e30f;
#pragma unroll
                for (int nt = 0; nt < 8; nt++) {
                    mx0 = fmaxf(mx0, fmaxf(s[nt][0], s[nt][1]));
                    mx1 = fmaxf(mx1, fmaxf(s[nt][2], s[nt][3]));
                }
                mx0 = fmaxf(mx0, __shfl_xor_sync(0xffffffffu, mx0, 1));
                mx0 = fmaxf(mx0, __shfl_xor_sync(0xffffffffu, mx0, 2));
                mx1 = fmaxf(mx1, __shfl_xor_sync(0xffffffffu, mx1, 1));
                mx1 = fmaxf(mx1, __shfl_xor_sync(0xffffffffu, mx1, 2));
                float nm0 = fmaxf(m_s[0], mx0), nm1 = fmaxf(m_s[1], mx1);
                float al0 = __expf(m_s[0] - nm0), al1 = __expf(m_s[1] - nm1);
                m_s[0] = nm0; m_s[1] = nm1;

                float sum0 = 0.f, sum1 = 0.f;
#pragma unroll
                for (int nt = 0; nt < 8; nt++) {
                    s[nt][0] = __expf(s[nt][0] - nm0);
                    s[nt][1] = __expf(s[nt][1] - nm0);
                    s[nt][2] = __expf(s[nt][2] - nm1);
                    s[nt][3] = __expf(s[nt][3] - nm1);
                    sum0 += s[nt][0] + s[nt][1];
                    sum1 += s[nt][2] + s[nt][3];
                }
                sum0 += __shfl_xor_sync(0xffffffffu, sum0, 1);
                sum0 += __shfl_xor_sync(0xffffffffu, sum0, 2);
                sum1 += __shfl_xor_sync(0xffffffffu, sum1, 1);
                sum1 += __shfl_xor_sync(0xffffffffu, sum1, 2);
                l_s[0] = l_s[0] * al0 + sum0;
                l_s[1] = l_s[1] * al1 + sum1;

#pragma unroll
                for (int nt = 0; nt < 8; nt++) {
                    acc[nt][0] *= al0; acc[nt][1] *= al0;
                    acc[nt][2] *= al1; acc[nt][3] *= al1;
                }
#pragma unroll
                for (int kk = 0; kk < 4; kk++) {
                    pa[kk][0] = pack_h2(s[2 * kk][0],     s[2 * kk][1]);
                    pa[kk][1] = pack_h2(s[2 * kk][2],     s[2 * kk][3]);
                    pa[kk][2] = pack_h2(s[2 * kk + 1][0], s[2 * kk + 1][1]);
                    pa[kk][3] = pack_h2(s[2 * kk + 1][2], s[2 * kk + 1][3]);
                }
            }

#pragma unroll
            for (int kk = 0; kk < 4; kk++) {
#pragma unroll
                for (int nt = 0; nt < 8; nt++) {
                    uint2 b = Vs[((kk << 3) | nt) * 32 + lane];
                    mma_f16(accA[nt], paA[kk], (const unsigned*)&b);
                    mma_f16(accB[nt], paB[kk], (const unsigned*)&b);
                }
            }

            cur ^= 1;
        }

#pragma unroll
        for (int u = 0; u < 2; u++) {
            float (*acc)[4] = u ? accB : accA;
            float* l_s = u ? lB : lA;
            int mt = u ? mtB : mtA;
            float inv0 = 1.0f / l_s[0];
            float inv1 = 1.0f / l_s[1];
#pragma unroll
            for (int kk = 0; kk < 4; kk++) {
                uint4 hi;
                hi.x = pack_h2(acc[2 * kk][0] * inv0,     acc[2 * kk][1] * inv0);
                hi.y = pack_h2(acc[2 * kk][2] * inv1,     acc[2 * kk][3] * inv1);
                hi.z = pack_h2(acc[2 * kk + 1][0] * inv0, acc[2 * kk + 1][1] * inv0);
                hi.w = pack_h2(acc[2 * kk + 1][2] * inv1, acc[2 * kk + 1][3] * inv1);
                g_attn_h[((size_t)mt * 64 + (h * 4 + kk)) * 32 + lane] = hi;
            }
        }
    }
}

// ---------------------------------------------------------------------------
extern "C" void kernel_launch(void* const* d_in, const int* in_sizes, int n_in,
                              void* d_out, int out_size)
{
    const int*   positions = (const int*)d_in[0];
    const float* hidden    = (const float*)d_in[1];
    const float* w_qkv     = (const float*)d_in[2];
    const float* w_o       = (const float*)d_in[3];
    float*       out       = (float*)d_out;

    float* qkv = nullptr;
    cudaGetSymbolAddress((void**)&qkv, g_qkv);
    uint4 *hidh, *attnh;
    uint2 *wqh, *wql, *woh, *wol;
    cudaGetSymbolAddress((void**)&hidh, g_hid_h);
    cudaGetSymbolAddress((void**)&attnh, g_attn_h);
    cudaGetSymbolAddress((void**)&wqh, g_wqkv_h);
    cudaGetSymbolAddress((void**)&wql, g_wqkv_l);
    cudaGetSymbolAddress((void**)&woh, g_wo_h);
    cudaGetSymbolAddress((void**)&wol, g_wo_l);

    // launch 0: merged rope table + input conversion (69632 warps)
    convert_all_kernel<<<(69632 * 32) / 256, 256>>>(positions, hidden, w_qkv, w_o);

    // launch 1: qkv = hidden @ w_qkv^T  (2-term fp16 tensor GEMM)
    gemm_frag_kernel<<<dim3(QKV_N / 128, S_LEN / 128), 256>>>(
        hidh, wqh, wql, qkv, QKV_N, IN_DIM / 16);

    // launch 2: qkv -> flash fp16 fragments with RoPE fused
    convert_frag_kernel<<<(7168 * 32) / 256, 256>>>();

    // launch 3: causal GQA flash attention (profiled slot)
    flash_tc_kernel<<<dim3(32, NKV), 256>>>();

    // launch 4: out = attn @ w_o^T  (2-term fp16 tensor GEMM)
    gemm_frag_kernel<<<dim3(HID / 128, S_LEN / 128), 256>>>(
        attnh, woh, wol, out, HID, QSIZE / 16);
}

// round 17
// speedup vs baseline: 1.0338x; 1.0338x over previous
#include <cuda_runtime.h>
#include <cuda_fp16.h>
#include <math.h>

#define S_LEN  4096
#define NH     16
#define NKV    4
#define HD     64
#define QSIZE  1024      // NH*HD
#define KVSIZE 256       // NKV*HD
#define QKV_N  1536      // QSIZE + 2*KVSIZE
#define IN_DIM 2048      // 2*HID
#define HID    1024
// Q pre-scale: (1/sqrt(HD)) * log2(e)  -> S lands in base-2 domain
#define QSCALE 0.18033688011112042f

// Scratch (device globals; no allocations allowed)
__device__ float g_qkv[S_LEN * QKV_N];             // raw qkv (pre-rope)
__device__ float2 g_rope_tab[S_LEN * 32];          // (cos,sin) per (s,j)
// flash fp16 fragment tensors
__device__ unsigned g_qf16[16 * 256 * 4 * 32 * 4]; // [h][mt][kk][lane][4]
__device__ unsigned g_kf16[4 * 512 * 4 * 32 * 2];  // [kvh][tb][kk][lane][2]
__device__ unsigned g_vf16[4 * 256 * 8 * 32 * 2];  // [kvh][t16][nt][lane][2]
// GEMM operand fragments: A single fp16, B split (hi+lo)
__device__ uint4 g_hid_h[256 * 128 * 32];          // hidden A-frag
__device__ uint2 g_wqkv_h[192 * 128 * 32];         // w_qkv B-frag hi
__device__ uint2 g_wqkv_l[192 * 128 * 32];         //             lo
__device__ uint2 g_wo_h[128 * 64 * 32];            // w_o B-frag hi
__device__ uint2 g_wo_l[128 * 64 * 32];
__device__ uint4 g_attn_h[256 * 64 * 32];          // attn A-frag

// ---------------------------------------------------------------------------
// helpers
// ---------------------------------------------------------------------------
__device__ __forceinline__ void mma_f16(float* c, const unsigned* a, const unsigned* b) {
    asm volatile(
        "mma.sync.aligned.m16n8k16.row.col.f32.f16.f16.f32 "
        "{%0,%1,%2,%3}, {%4,%5,%6,%7}, {%8,%9}, {%0,%1,%2,%3};"
        : "+f"(c[0]), "+f"(c[1]), "+f"(c[2]), "+f"(c[3])
        : "r"(a[0]), "r"(a[1]), "r"(a[2]), "r"(a[3]), "r"(b[0]), "r"(b[1]));
}

__device__ __forceinline__ unsigned pack_h2(float lo, float hi) {
    __half2 h = __floats2half2_rn(lo, hi);
    return *(unsigned*)&h;
}

__device__ __forceinline__ unsigned ex2_h2(unsigned x) {
    unsigned r;
    asm("ex2.approx.f16x2 %0, %1;" : "=r"(r) : "r"(x));
    return r;
}

__device__ __forceinline__ void split_h2(float a, float b, unsigned& hi, unsigned& lo) {
    __half ha = __float2half_rn(a), hb = __float2half_rn(b);
    float ra = a - __half2float(ha), rb = b - __half2float(hb);
    __half2 h = __halves2half2(ha, hb);
    hi = *(unsigned*)&h;
    lo = pack_h2(ra, rb);
}

__device__ __forceinline__ void cp_async16(void* smem, const void* gmem) {
    unsigned s = (unsigned)__cvta_generic_to_shared(smem);
    asm volatile("cp.async.cg.shared.global [%0], [%1], 16;" :: "r"(s), "l"(gmem));
}
#define CP_COMMIT() asm volatile("cp.async.commit_group;")
#define CP_WAIT_ALL() asm volatile("cp.async.wait_group 0;")

// ---------------------------------------------------------------------------
// MERGED: rope table + input conversion (one launch).
// ---------------------------------------------------------------------------
__global__ __launch_bounds__(256) void convert_all_kernel(
    const int* __restrict__ positions,
    const float* __restrict__ hidden, const float* __restrict__ w_qkv,
    const float* __restrict__ w_o)
{
    const int wid  = (blockIdx.x * blockDim.x + threadIdx.x) >> 5;
    const int lane = threadIdx.x & 31;
    const int g = lane >> 2, t = lane & 3;

    if (wid < 4096) {
        double invf = exp(-(double)lane * (1.0 / 32.0) * log(10000.0));
        float f = (float)positions[wid] * (float)invf;
        float sn, c;
        sincosf(f, &sn, &c);
        g_rope_tab[wid * 32 + lane] = make_float2(c, sn);
    } else if (wid < 4096 + 32768) {
        const int u = wid - 4096;
        const int mt = u >> 7, kk = u & 127;
        const float* A = hidden + (size_t)(mt * 16) * IN_DIM + kk * 16;
        float2 a0 = *(const float2*)(A + (size_t)g * IN_DIM + 2 * t);
        float2 a1 = *(const float2*)(A + (size_t)(g + 8) * IN_DIM + 2 * t);
        float2 a2 = *(const float2*)(A + (size_t)g * IN_DIM + 2 * t + 8);
        float2 a3 = *(const float2*)(A + (size_t)(g + 8) * IN_DIM + 2 * t + 8);
        uint4 h;
        h.x = pack_h2(a0.x, a0.y);
        h.y = pack_h2(a1.x, a1.y);
        h.z = pack_h2(a2.x, a2.y);
        h.w = pack_h2(a3.x, a3.y);
        g_hid_h[(size_t)u * 32 + lane] = h;
    } else if (wid < 4096 + 32768 + 24576) {
        const int u = wid - 4096 - 32768;
        const int nt = u >> 7, kk = u & 127;
        const float* B = w_qkv + (size_t)(nt * 8 + g) * IN_DIM + kk * 16;
        float2 b0 = *(const float2*)(B + 2 * t);
        float2 b1 = *(const float2*)(B + 2 * t + 8);
        uint2 h, l;
        split_h2(b0.x, b0.y, h.x, l.x);
        split_h2(b1.x, b1.y, h.y, l.y);
        size_t o = (size_t)u * 32 + lane;
        g_wqkv_h[o] = h; g_wqkv_l[o] = l;
    } else if (wid < 4096 + 32768 + 24576 + 8192) {
        const int u = wid - 4096 - 32768 - 24576;
        const int nt = u >> 6, kk = u & 63;
        const float* B = w_o + (size_t)(nt * 8 + g) * QSIZE + kk * 16;
        float2 b0 = *(const float2*)(B + 2 * t);
        float2 b1 = *(const float2*)(B + 2 * t + 8);
        uint2 h, l;
        split_h2(b0.x, b0.y, h.x, l.x);
        split_h2(b1.x, b1.y, h.y, l.y);
        size_t o = (size_t)u * 32 + lane;
        g_wo_h[o] = h; g_wo_l[o] = l;
    }
}

// ---------------------------------------------------------------------------
// NT GEMM on fragment-major operands, A single fp16, B split (R14-validated)
// ---------------------------------------------------------------------------
__global__ __launch_bounds__(256, 1) void gemm_frag_kernel(
    const uint4* __restrict__ Ah,
    const uint2* __restrict__ Bh, const uint2* __restrict__ Bl,
    float* __restrict__ C, int Nn, int Kk)
{
    const int lane = threadIdx.x & 31;
    const int w = threadIdx.x >> 5;
    const int mt0 = blockIdx.y * 8 + (w >> 2) * 4;
    const int nt0 = blockIdx.x * 16 + (w & 3) * 4;

    const uint4 *pah[4];
    const uint2 *pbh[4], *pbl[4];
#pragma unroll
    for (int i = 0; i < 4; i++) {
        size_t oa = ((size_t)(mt0 + i) * Kk) * 32 + lane;
        size_t ob = ((size_t)(nt0 + i) * Kk) * 32 + lane;
        pah[i] = Ah + oa;
        pbh[i] = Bh + ob; pbl[i] = Bl + ob;
    }

    float acc[4][4][4];
#pragma unroll
    for (int i = 0; i < 4; i++)
#pragma unroll
        for (int j = 0; j < 4; j++)
#pragma unroll
            for (int e = 0; e < 4; e++) acc[i][j][e] = 0.f;

    uint4 ah[2][4];
    uint2 bh[2][4], bl[2][4];
#pragma unroll
    for (int i = 0; i < 4; i++) {
        ah[0][i] = pah[i][0];
        bh[0][i] = pbh[i][0]; bl[0][i] = pbl[i][0];
    }

    for (int kk = 0; kk < Kk; kk++) {
        const int cur = kk & 1, nxt = cur ^ 1;
        if (kk + 1 < Kk) {
            int off = (kk + 1) * 32;
#pragma unroll
            for (int i = 0; i < 4; i++) {
                ah[nxt][i] = pah[i][off];
                bh[nxt][i] = pbh[i][off]; bl[nxt][i] = pbl[i][off];
            }
        }
#pragma unroll
        for (int i = 0; i < 4; i++)
#pragma unroll
            for (int j = 0; j < 4; j++) {
                mma_f16(acc[i][j], (const unsigned*)&ah[cur][i], (const unsigned*)&bh[cur][j]);
                mma_f16(acc[i][j], (const unsigned*)&ah[cur][i], (const unsigned*)&bl[cur][j]);
            }
    }

    const int g = lane >> 2, tq = lane & 3;
#pragma unroll
    for (int i = 0; i < 4; i++) {
        int r0 = (mt0 + i) * 16 + g;
#pragma unroll
        for (int j = 0; j < 4; j++) {
            int c0 = (nt0 + j) * 8 + tq * 2;
            float2 lo = {acc[i][j][0], acc[i][j][1]};
            float2 hi = {acc[i][j][2], acc[i][j][3]};
            *(float2*)(C + (size_t)r0 * Nn + c0)       = lo;
            *(float2*)(C + (size_t)(r0 + 8) * Nn + c0) = hi;
        }
    }
}

// ---------------------------------------------------------------------------
// Convert qkv -> flash fp16 fragments WITH RoPE fused.
// Q scale now folds log2(e): S emerges in base-2 domain.
// ---------------------------------------------------------------------------
__global__ __launch_bounds__(256) void convert_frag_kernel()
{
    const int wid  = (blockIdx.x * blockDim.x + threadIdx.x) >> 5;
    const int lane = threadIdx.x & 31;
    const int g = lane >> 2, t = lane & 3;

    if (wid < 4096) {
        const int h = wid >> 8, mt = wid & 255;
        const int s0 = mt * 16;
        const float* Q = g_qkv + (size_t)s0 * QKV_N + h * 64;
        unsigned* dst = g_qf16 + ((size_t)(h * 256 + mt) * 4) * 128;
#pragma unroll
        for (int kk = 0; kk < 2; kk++) {
            int c = kk * 16 + 2 * t;
            uint4 wl, wh;
            unsigned* pl = (unsigned*)&wl;
            unsigned* ph = (unsigned*)&wh;
#pragma unroll
            for (int pi = 0; pi < 2; pi++) {
                int cc = c + pi * 8;
#pragma unroll
                for (int ri = 0; ri < 2; ri++) {
                    int r = g + ri * 8;
                    float2 xa = *(const float2*)(Q + (size_t)r * QKV_N + cc);
                    float2 xb = *(const float2*)(Q + (size_t)r * QKV_N + cc + 32);
                    float4 tb = *(const float4*)(g_rope_tab + (size_t)(s0 + r) * 32 + cc);
                    pl[pi * 2 + ri] = pack_h2((xa.x * tb.x - xb.x * tb.y) * QSCALE,
                                              (xa.y * tb.z - xb.y * tb.w) * QSCALE);
                    ph[pi * 2 + ri] = pack_h2((xb.x * tb.x + xa.x * tb.y) * QSCALE,
                                              (xb.y * tb.z + xa.y * tb.w) * QSCALE);
                }
            }
            *(uint4*)(dst + ((kk * 32 + lane) << 2))       = wl;
            *(uint4*)(dst + (((kk + 2) * 32 + lane)) * 4)  = wh;
        }
    } else if (wid < 4096 + 2048) {
        const int u = wid - 4096;
        const int kvh = u >> 9, tb = u & 511;
        const int s = tb * 8 + g;
        const float* K = g_qkv + (size_t)s * QKV_N + QSIZE + kvh * 64;
        unsigned* dst = g_kf16 + ((size_t)(kvh * 512 + tb) * 4) * 64;
#pragma unroll
        for (int kk = 0; kk < 2; kk++) {
            int c = kk * 16 + 2 * t;
            uint2 wl, wh;
            unsigned* pl = (unsigned*)&wl;
            unsigned* ph = (unsigned*)&wh;
#pragma unroll
            for (int pi = 0; pi < 2; pi++) {
                int cc = c + pi * 8;
                float2 xa = *(const float2*)(K + cc);
                float2 xb = *(const float2*)(K + cc + 32);
                float4 tbv = *(const float4*)(g_rope_tab + (size_t)s * 32 + cc);
                pl[pi] = pack_h2(xa.x * tbv.x - xb.x * tbv.y,
                                 xa.y * tbv.z - xb.y * tbv.w);
                ph[pi] = pack_h2(xb.x * tbv.x + xa.x * tbv.y,
                                 xb.y * tbv.z + xa.y * tbv.w);
            }
            *(uint2*)(dst + ((kk * 32 + lane) << 1))      = wl;
            *(uint2*)(dst + (((kk + 2) * 32 + lane)) * 2) = wh;
        }
    } else if (wid < 4096 + 2048 + 1024) {
        const int u = wid - 4096 - 2048;
        const int kvh = u >> 8, t16 = u & 255;
        const float* V = g_qkv + (size_t)(t16 * 16) * QKV_N + QSIZE + KVSIZE + kvh * 64;
        unsigned* dst = g_vf16 + ((size_t)(kvh * 256 + t16) * 8) * 64;
#pragma unroll
        for (int nt = 0; nt < 8; nt++) {
            int d = nt * 8 + g;
            float v0 = V[(size_t)(2 * t) * QKV_N + d];
            float v1 = V[(size_t)(2 * t + 1) * QKV_N + d];
            float v2 = V[(size_t)(2 * t + 8) * QKV_N + d];
            float v3 = V[(size_t)(2 * t + 9) * QKV_N + d];
            uint2 w;
            w.x = pack_h2(v0, v1);
            w.y = pack_h2(v2, v3);
            *(uint2*)(dst + ((nt * 32 + lane) << 1)) = w;
        }
    }
}

// ---------------------------------------------------------------------------
// Causal GQA flash attention — MUFU-optimized softmax:
//  * S in base-2 domain (Q pre-scaled by log2e/8)
//  * P = ex2.approx.f16x2 on packed pairs (half the MUFU ops; output IS the
//    mma A-fragment)
//  * row sums l via ones-MMA (no FADD reduction, no shuffles; l lives in an
//    fp32 mma accumulator scaled by alpha like acc_o)
// 8 warps, 2 m-tiles/warp, paired qb, cp.async double buffer (R15 shape).
// ---------------------------------------------------------------------------
__global__ __launch_bounds__(256, 1) void flash_tc_kernel()
{
    __shared__ __align__(16) unsigned smK[2][2048];
    __shared__ __align__(16) unsigned smV[2][2048];

    const int tid  = threadIdx.x;
    const int lane = tid & 31;
    const int wrp  = tid >> 5;
    const int hw   = wrp >> 1;
    const int mp   = wrp & 1;
    const int pair = blockIdx.x;
    const int kvh = blockIdx.y;
    const int h = kvh * 4 + hw;

    const int gq = lane >> 2;
    const int tq = lane & 3;
    const int qrowA = (mp * 32) + gq;
    const int qrowB = (mp * 32) + 16 + gq;

    const unsigned ones2 = 0x3C003C00u;          // half2(1,1)
    const unsigned onesb[2] = {ones2, ones2};    // all-ones B fragment

    const unsigned* kf0 = g_kf16 + (size_t)kvh * 512 * 4 * 64;
    const unsigned* vf0 = g_vf16 + (size_t)kvh * 256 * 8 * 64;

    cp_async16(&smK[0][tid * 8],     kf0 + tid * 8);
    cp_async16(&smK[0][tid * 8 + 4], kf0 + tid * 8 + 4);
    cp_async16(&smV[0][tid * 8],     vf0 + tid * 8);
    cp_async16(&smV[0][tid * 8 + 4], vf0 + tid * 8 + 4);
    CP_COMMIT();

    int cur = 0;

#pragma unroll
    for (int half = 0; half < 2; half++) {
        const int qb = half ? pair : (63 - pair);
        const int mtA = qb * 4 + mp * 2;
        const int mtB = mtA + 1;

        unsigned qaA[4][4], qaB[4][4];
        {
            const uint4* qfA = (const uint4*)g_qf16 + ((size_t)(h * 256 + mtA) * 4) * 32;
            const uint4* qfB = (const uint4*)g_qf16 + ((size_t)(h * 256 + mtB) * 4) * 32;
#pragma unroll
            for (int kk = 0; kk < 4; kk++) {
                *(uint4*)qaA[kk] = qfA[kk * 32 + lane];
                *(uint4*)qaB[kk] = qfB[kk * 32 + lane];
            }
        }

        float mA[2] = {-1e30f, -1e30f};
        float mB[2] = {-1e30f, -1e30f};
        float accA[8][4], accB[8][4];
        float lacA[4], lacB[4];                  // l accumulators (ones-MMA)
#pragma unroll
        for (int i = 0; i < 8; i++)
#pragma unroll
            for (int j = 0; j < 4; j++) { accA[i][j] = 0.f; accB[i][j] = 0.f; }
#pragma unroll
        for (int j = 0; j < 4; j++) { lacA[j] = 0.f; lacB[j] = 0.f; }

        for (int kb = 0; kb <= qb; kb++) {
            const int nxt = cur ^ 1;
            CP_WAIT_ALL();
            __syncthreads();

            const bool more = (kb < qb);
            if (more) {
                const unsigned* kn = kf0 + (size_t)(kb + 1) * 2048;
                const unsigned* vn = vf0 + (size_t)(kb + 1) * 2048;
                cp_async16(&smK[nxt][tid * 8],     kn + tid * 8);
                cp_async16(&smK[nxt][tid * 8 + 4], kn + tid * 8 + 4);
                cp_async16(&smV[nxt][tid * 8],     vn + tid * 8);
                cp_async16(&smV[nxt][tid * 8 + 4], vn + tid * 8 + 4);
                CP_COMMIT();
            } else if (half == 0) {
                cp_async16(&smK[nxt][tid * 8],     kf0 + tid * 8);
                cp_async16(&smK[nxt][tid * 8 + 4], kf0 + tid * 8 + 4);
                cp_async16(&smV[nxt][tid * 8],     vf0 + tid * 8);
                cp_async16(&smV[nxt][tid * 8 + 4], vf0 + tid * 8 + 4);
                CP_COMMIT();
            }

            const uint2* Ks = (const uint2*)smK[cur];
            const uint2* Vs = (const uint2*)smV[cur];

            float sA[8][4], sB[8][4];
#pragma unroll
            for (int nt = 0; nt < 8; nt++)
#pragma unroll
                for (int j = 0; j < 4; j++) { sA[nt][j] = 0.f; sB[nt][j] = 0.f; }
#pragma unroll
            for (int kk = 0; kk < 4; kk++) {
#pragma unroll
                for (int nt = 0; nt < 8; nt++) {
                    uint2 b = Ks[((nt << 2) | kk) * 32 + lane];
                    mma_f16(sA[nt], qaA[kk], (const unsigned*)&b);
                    mma_f16(sB[nt], qaB[kk], (const unsigned*)&b);
                }
            }

            if (kb == qb) {
#pragma unroll
                for (int nt = 0; nt < 8; nt++) {
                    int cb = (nt << 3) + (tq << 1);
                    if (cb     > qrowA)     sA[nt][0] = -1e30f;
                    if (cb + 1 > qrowA)     sA[nt][1] = -1e30f;
                    if (cb     > qrowA + 8) sA[nt][2] = -1e30f;
                    if (cb + 1 > qrowA + 8) sA[nt][3] = -1e30f;
                    if (cb     > qrowB)     sB[nt][0] = -1e30f;
                    if (cb + 1 > qrowB)     sB[nt][1] = -1e30f;
                    if (cb     > qrowB + 8) sB[nt][2] = -1e30f;
                    if (cb + 1 > qrowB + 8) sB[nt][3] = -1e30f;
                }
            }

            // ---- online softmax (base-2), P via ex2.f16x2, l via ones-MMA ----
            unsigned paA[4][4], paB[4][4];
#pragma unroll
            for (int u = 0; u < 2; u++) {
                float (*s)[4]   = u ? sB : sA;
                float* m_s      = u ? mB : mA;
                float (*acc)[4] = u ? accB : accA;
                float* lac      = u ? lacB : lacA;
                unsigned (*pa)[4] = u ? paB : paA;

                float mx0 = -1e30f, mx1 = -1e30f;
#pragma unroll
                for (int nt = 0; nt < 8; nt++) {
                    mx0 = fmaxf(mx0, fmaxf(s[nt][0], s[nt][1]));
                    mx1 = fmaxf(mx1, fmaxf(s[nt][2], s[nt][3]));
                }
                mx0 = fmaxf(mx0, __shfl_xor_sync(0xffffffffu, mx0, 1));
                mx0 = fmaxf(mx0, __shfl_xor_sync(0xffffffffu, mx0, 2));
                mx1 = fmaxf(mx1, __shfl_xor_sync(0xffffffffu, mx1, 1));
                mx1 = fmaxf(mx1, __shfl_xor_sync(0xffffffffu, mx1, 2));
                float nm0 = fmaxf(m_s[0], mx0), nm1 = fmaxf(m_s[1], mx1);
                float al0 = exp2f(m_s[0] - nm0), al1 = exp2f(m_s[1] - nm1);
                m_s[0] = nm0; m_s[1] = nm1;

#pragma unroll
                for (int nt = 0; nt < 8; nt++) {
                    acc[nt][0] *= al0; acc[nt][1] *= al0;
                    acc[nt][2] *= al1; acc[nt][3] *= al1;
                }
                lac[0] *= al0; lac[1] *= al0;
                lac[2] *= al1; lac[3] *= al1;

#pragma unroll
                for (int kk = 0; kk < 4; kk++) {
                    pa[kk][0] = ex2_h2(pack_h2(s[2 * kk][0] - nm0,     s[2 * kk][1] - nm0));
                    pa[kk][1] = ex2_h2(pack_h2(s[2 * kk][2] - nm1,     s[2 * kk][3] - nm1));
                    pa[kk][2] = ex2_h2(pack_h2(s[2 * kk + 1][0] - nm0, s[2 * kk + 1][1] - nm0));
                    pa[kk][3] = ex2_h2(pack_h2(s[2 * kk + 1][2] - nm1, s[2 * kk + 1][3] - nm1));
                    mma_f16(lac, pa[kk], onesb);   // l += P @ 1
                }
            }

            // ---- PV for both m-tiles (B loaded once) ----
#pragma unroll
            for (int kk = 0; kk < 4; kk++) {
#pragma unroll
                for (int nt = 0; nt < 8; nt++) {
                    uint2 b = Vs[((kk << 3) | nt) * 32 + lane];
                    mma_f16(accA[nt], paA[kk], (const unsigned*)&b);
                    mma_f16(accB[nt], paB[kk], (const unsigned*)&b);
                }
            }

            cur ^= 1;
        }

        // ---- epilogue: normalize + emit single-fp16 A-fragments of attn ----
#pragma unroll
        for (int u = 0; u < 2; u++) {
            float (*acc)[4] = u ? accB : accA;
            float* lac = u ? lacB : lacA;
            int mt = u ? mtB : mtA;
            float inv0 = 1.0f / lac[0];
            float inv1 = 1.0f / lac[2];
#pragma unroll
            for (int kk = 0; kk < 4; kk++) {
                uint4 hi;
                hi.x = pack_h2(acc[2 * kk][0] * inv0,     acc[2 * kk][1] * inv0);
                hi.y = pack_h2(acc[2 * kk][2] * inv1,     acc[2 * kk][3] * inv1);
                hi.z = pack_h2(acc[2 * kk + 1][0] * inv0, acc[2 * kk + 1][1] * inv0);
                hi.w = pack_h2(acc[2 * kk + 1][2] * inv1, acc[2 * kk + 1][3] * inv1);
                g_attn_h[((size_t)mt * 64 + (h * 4 + kk)) * 32 + lane] = hi;
            }
        }
    }
}

// ---------------------------------------------------------------------------
extern "C" void kernel_launch(void* const* d_in, const int* in_sizes, int n_in,
                              void* d_out, int out_size)
{
    const int*   positions = (const int*)d_in[0];
    const float* hidden    = (const float*)d_in[1];
    const float* w_qkv     = (const float*)d_in[2];
    const float* w_o       = (const float*)d_in[3];
    float*       out       = (float*)d_out;

    float* qkv = nullptr;
    cudaGetSymbolAddress((void**)&qkv, g_qkv);
    uint4 *hidh, *attnh;
    uint2 *wqh, *wql, *woh, *wol;
    cudaGetSymbolAddress((void**)&hidh, g_hid_h);
    cudaGetSymbolAddress((void**)&attnh, g_attn_h);
    cudaGetSymbolAddress((void**)&wqh, g_wqkv_h);
    cudaGetSymbolAddress((void**)&wql, g_wqkv_l);
    cudaGetSymbolAddress((void**)&woh, g_wo_h);
    cudaGetSymbolAddress((void**)&wol, g_wo_l);

    // launch 0: merged rope table + input conversion
    convert_all_kernel<<<(69632 * 32) / 256, 256>>>(positions, hidden, w_qkv, w_o);

    // launch 1: qkv = hidden @ w_qkv^T
    gemm_frag_kernel<<<dim3(QKV_N / 128, S_LEN / 128), 256>>>(
        hidh, wqh, wql, qkv, QKV_N, IN_DIM / 16);

    // launch 2: qkv -> flash fp16 fragments with RoPE fused (log2e folded)
    convert_frag_kernel<<<(7168 * 32) / 256, 256>>>();

    // launch 3: causal GQA flash attention (profiled slot)
    flash_tc_kernel<<<dim3(32, NKV), 256>>>();

    // launch 4: out = attn @ w_o^T
    gemm_frag_kernel<<<dim3(HID / 128, S_LEN / 128), 256>>>(
        attnh, woh, wol, out, HID, QSIZE / 16);
}